// round 14
// baseline (speedup 1.0000x reference)
#include <cuda_runtime.h>
#include <cuda_fp16.h>
#include <stdint.h>
#include <math.h>

// Problem constants
#define BB   4
#define TTT  4096
#define CC   1024
#define HH   16
#define KD   64          // head dim
#define TCH  128         // chunk length
#define NCH  32          // chunks
#define MM   (BB*TTT)    // 16384 rows

// ---------------- scratch (device globals; no allocation allowed) ----------
__device__ __half g_xr[MM*CC];
__device__ __half g_xk[MM*CC];
__device__ __half g_xv[MM*CC];
__device__ __half g_xg[MM*CC];
__device__ __half g_z [MM*CC];
__device__ __half g_wr[CC*CC];
__device__ __half g_wk[CC*CC];
__device__ __half g_wv[CC*CC];
__device__ __half g_wg[CC*CC];
__device__ __half g_wo[CC*CC];
__device__ float g_r [MM*CC];
__device__ float g_k [MM*CC];
__device__ float g_v [MM*CC];
__device__ float g_g [MM*CC];
__device__ float g_states[BB*HH*NCH*KD*KD];

// ---------------- helpers ---------------------------------------------------
__device__ __forceinline__ void mma_f16(float* c, const uint32_t* a,
                                        uint32_t b0, uint32_t b1) {
    asm volatile(
        "mma.sync.aligned.m16n8k16.row.col.f32.f16.f16.f32 "
        "{%0,%1,%2,%3}, {%4,%5,%6,%7}, {%8,%9}, {%0,%1,%2,%3};"
        : "+f"(c[0]), "+f"(c[1]), "+f"(c[2]), "+f"(c[3])
        : "r"(a[0]), "r"(a[1]), "r"(a[2]), "r"(a[3]), "r"(b0), "r"(b1));
}

__device__ __forceinline__ uint32_t smem_u32(const void* p) {
    uint32_t a;
    asm("{ .reg .u64 t; cvta.to.shared.u64 t, %1; cvt.u32.u64 %0, t; }"
        : "=r"(a) : "l"(p));
    return a;
}
__device__ __forceinline__ void cp16(uint32_t saddr, const void* g) {
    asm volatile("cp.async.cg.shared.global [%0], [%1], 16;" :: "r"(saddr), "l"(g));
}
__device__ __forceinline__ void cp_commit() {
    asm volatile("cp.async.commit_group;");
}
__device__ __forceinline__ void cp_wait1() {
    asm volatile("cp.async.wait_group 1;");
}
__device__ __forceinline__ void ldsm4(uint32_t* r, uint32_t addr) {
    asm volatile("ldmatrix.sync.aligned.m8n8.x4.shared.b16 {%0,%1,%2,%3}, [%4];"
                 : "=r"(r[0]), "=r"(r[1]), "=r"(r[2]), "=r"(r[3]) : "r"(addr));
}
__device__ __forceinline__ void ldsm4t(uint32_t* r, uint32_t addr) {
    asm volatile("ldmatrix.sync.aligned.m8n8.x4.trans.shared.b16 {%0,%1,%2,%3}, [%4];"
                 : "=r"(r[0]), "=r"(r[1]), "=r"(r[2]), "=r"(r[3]) : "r"(addr));
}

__device__ __forceinline__ uint32_t h2pack(float a, float b) {
    __half2 h(__float2half_rn(a), __float2half_rn(b));
    return *(uint32_t*)&h;
}

// swizzled byte offset within a 128-row x 64B tile: row r, 16B-unit u (0..3)
__device__ __forceinline__ uint32_t swz(int r, int u) {
    return (uint32_t)(r * 64 + ((u ^ ((r >> 1) & 3)) << 4));
}
// 128B rows (64 fp16): unit u 0..7
__device__ __forceinline__ uint32_t swz64(int r, int u) {
    return (uint32_t)(r * 128 + ((u ^ (r & 7)) << 4));
}
// 256B rows (128 fp16): unit u 0..15
__device__ __forceinline__ uint32_t swzA(int r, int u) {
    int phys = (u & 8) | ((u ^ (r & 7)) & 7);
    return (uint32_t)(r * 256 + phys * 16);
}

// ---------------- 0) weight convert fp32 -> fp16 (all 5 fused) -------------
__global__ void wsplit5_kernel(const float* __restrict__ W0, const float* __restrict__ W1,
                               const float* __restrict__ W2, const float* __restrict__ W3,
                               const float* __restrict__ W4,
                               __half* __restrict__ H0, __half* __restrict__ H1,
                               __half* __restrict__ H2, __half* __restrict__ H3,
                               __half* __restrict__ H4) {
    int i = blockIdx.x * blockDim.x + threadIdx.x;
    const float* W; __half* Hh;
    switch (blockIdx.y) {
        case 0: W = W0; Hh = H0; break;
        case 1: W = W1; Hh = H1; break;
        case 2: W = W2; Hh = H2; break;
        case 3: W = W3; Hh = H3; break;
        default: W = W4; Hh = H4; break;
    }
    Hh[i] = __float2half_rn(W[i]);
}

// ---------------- 1) time-shift mixing -> fp16 (float4 vectorized) ---------
__device__ __forceinline__ void mix4_store(const float* __restrict__ tm, int c,
                                           float4 xc, float4 xp,
                                           __half* __restrict__ H, int idx) {
    float4 m = *(const float4*)(tm + c);
    float y0 = xc.x * m.x + xp.x * (1.f - m.x);
    float y1 = xc.y * m.y + xp.y * (1.f - m.y);
    float y2 = xc.z * m.z + xp.z * (1.f - m.z);
    float y3 = xc.w * m.w + xp.w * (1.f - m.w);
    uint2 hv = make_uint2(h2pack(y0, y1), h2pack(y2, y3));
    *(uint2*)(H + idx) = hv;
}

__global__ void mix_kernel(const float* __restrict__ x,
                           const float* __restrict__ tmk,
                           const float* __restrict__ tmv,
                           const float* __restrict__ tmr,
                           const float* __restrict__ tmg) {
    int idx = (blockIdx.x * blockDim.x + threadIdx.x) * 4;
    int c = idx & (CC - 1);
    int t = (idx >> 10) & (TTT - 1);
    float4 xc = *(const float4*)(x + idx);
    float4 xp = t ? *(const float4*)(x + idx - CC) : make_float4(0.f, 0.f, 0.f, 0.f);
    mix4_store(tmr, c, xc, xp, g_xr, idx);
    mix4_store(tmk, c, xc, xp, g_xk, idx);
    mix4_store(tmv, c, xc, xp, g_xv, idx);
    mix4_store(tmg, c, xc, xp, g_xg, idx);
}

// ---------------- 2) mma.sync GEMM: C = A @ W^T (fp16, K-chunk 32) ---------
// CTA tile 128x128, 8 warps (warp tile 32x64), K-chunk 32.
// 3-stage cp.async, 48KB smem, 2 CTAs/SM.  (Round-12 proven config.)
#define KCH     32
#define TILE_B  8192                     // 128 rows x 64B
#define BUF_B   (2*TILE_B)               // A, B
#define GSM_TOTAL (3*BUF_B)              // 49152 B
#define NKC     (CC/KCH)                 // 32 chunks

__global__ void __launch_bounds__(256, 2)
gemm_mma(const __half* __restrict__ A0, const __half* __restrict__ B0,
         float* __restrict__ C0,
         const __half* __restrict__ A1, const __half* __restrict__ B1,
         float* __restrict__ C1,
         const __half* __restrict__ A2, const __half* __restrict__ B2,
         float* __restrict__ C2,
         const __half* __restrict__ A3, const __half* __restrict__ B3,
         float* __restrict__ C3) {
    extern __shared__ char dsm[];
    uint32_t sbase = smem_u32(dsm);
    int tid = threadIdx.x;
    int w   = tid >> 5;
    int lane = tid & 31;
    int g = lane >> 2;
    int t = lane & 3;
    int n0 = blockIdx.x * 128;
    int m0 = blockIdx.y * 128;
    int m0w = (w >> 1) * 32;
    int n0w = (w & 1) * 64;

    const __half *Aa, *Bw; float* C;
    switch (blockIdx.z) {
        case 0: Aa = A0; Bw = B0; C = C0; break;
        case 1: Aa = A1; Bw = B1; C = C1; break;
        case 2: Aa = A2; Bw = B2; C = C2; break;
        default: Aa = A3; Bw = B3; C = C3; break;
    }
    const __half* sA = Aa + (size_t)m0 * CC;
    const __half* sB = Bw + (size_t)n0 * CC;

    int r0 = tid >> 2, u = tid & 3;
    size_t go0 = (size_t)r0 * CC + u * 8;
    size_t go1 = go0 + (size_t)64 * CC;
    uint32_t so0 = swz(r0, u);
    uint32_t so1 = so0 + 64 * 64;

    int arow = lane & 15;
    int akof = (lane >> 4) << 3;
    int brow = ((lane >> 4) << 3) + (lane & 7);
    int bkof = ((lane >> 3) & 1) << 3;
    int rowA0 = m0w + arow, rowA1 = m0w + 16 + arow;

    float acc[2][8][4];
#pragma unroll
    for (int mi = 0; mi < 2; mi++)
#pragma unroll
        for (int ni = 0; ni < 8; ni++)
#pragma unroll
            for (int q = 0; q < 4; q++) acc[mi][ni][q] = 0.f;

    auto issue = [&](int chunk) {
        int k0 = chunk * KCH;
        uint32_t b = sbase + (uint32_t)((chunk % 3) * BUF_B);
        cp16(b + 0*TILE_B + so0, sA + go0 + k0); cp16(b + 0*TILE_B + so1, sA + go1 + k0);
        cp16(b + 1*TILE_B + so0, sB + go0 + k0); cp16(b + 1*TILE_B + so1, sB + go1 + k0);
        cp_commit();
    };

    issue(0);
    issue(1);

    for (int c = 0; c < NKC; ++c) {
        cp_wait1();
        __syncthreads();
        if (c + 2 < NKC) issue(c + 2);

        uint32_t sb = sbase + (uint32_t)((c % 3) * BUF_B);
        uint32_t tA = sb;
        uint32_t tB = sb + TILE_B;
#pragma unroll
        for (int ks = 0; ks < 2; ++ks) {
            int kk = ks * 16;
            int uA = (kk + akof) >> 3;
            uint32_t ah[2][4];
            {
                ldsm4(ah[0], tA + swz(rowA0, uA));
                ldsm4(ah[1], tA + swz(rowA1, uA));
            }
            int uB = (kk + bkof) >> 3;
#pragma unroll
            for (int np = 0; np < 4; np++) {
                uint32_t b4[4];
                ldsm4(b4, tB + swz(n0w + np * 16 + brow, uB));
#pragma unroll
                for (int sub = 0; sub < 2; sub++) {
                    int ni = np * 2 + sub;
                    uint32_t b0 = b4[sub * 2], b1 = b4[sub * 2 + 1];
#pragma unroll
                    for (int mi = 0; mi < 2; mi++)
                        mma_f16(acc[mi][ni], ah[mi], b0, b1);
                }
            }
        }
    }

#pragma unroll
    for (int mi = 0; mi < 2; mi++) {
        int r = m0 + m0w + mi * 16 + g;
#pragma unroll
        for (int ni = 0; ni < 8; ni++) {
            int col = n0 + n0w + ni * 8 + 2 * t;
            *(float2*)&C[(size_t)r * CC + col] =
                make_float2(acc[mi][ni][0], acc[mi][ni][1]);
            *(float2*)&C[(size_t)(r + 8) * CC + col] =
                make_float2(acc[mi][ni][2], acc[mi][ni][3]);
        }
    }
}

// ---------------- shared convert helper: 8 fp32 -> fp16 hi/lo swizzled -----
__device__ __forceinline__ void cvt8_vals(float4 f0, float4 f1, char* smbase,
                                          uint32_t offH, uint32_t offL,
                                          int row, int uu) {
    uint4 hi = make_uint4(h2pack(f0.x, f0.y), h2pack(f0.z, f0.w),
                          h2pack(f1.x, f1.y), h2pack(f1.z, f1.w));
    uint32_t sw = swz64(row, uu);
    *(uint4*)(smbase + offH + sw) = hi;
    __half2* hp = (__half2*)&hi;
    uint4 lo = make_uint4(
        h2pack(f0.x - __half2float(hp[0].x), f0.y - __half2float(hp[0].y)),
        h2pack(f0.z - __half2float(hp[1].x), f0.w - __half2float(hp[1].y)),
        h2pack(f1.x - __half2float(hp[2].x), f1.y - __half2float(hp[2].y)),
        h2pack(f1.z - __half2float(hp[3].x), f1.w - __half2float(hp[3].y)));
    *(uint4*)(smbase + offL + sw) = lo;
}
__device__ __forceinline__ void cvt8_store(const float* src, char* smbase,
                                           uint32_t offH, uint32_t offL,
                                           int row, int uu) {
    float4 f0 = *(const float4*)(src);
    float4 f1 = *(const float4*)(src + 4);
    cvt8_vals(f0, f1, smbase, offH, offL, row, uu);
}

// ---------------- 3a) per-chunk state contributions via mma.sync -----------
// A_n[kk][vv] = sum_j (k[j][kk]*dp[j]) * v[j][vv] : GEMM M=64,N=64,K=128.
#define ST_KW_H 0
#define ST_KW_L 16384
#define ST_V_H  32768
#define ST_V_L  49152
#define ST_DP   65536        // 128 floats
#define ST_TOTAL 66048

__global__ void __launch_bounds__(256, 2)
stateA_kernel(const float* __restrict__ tdecay) {
    extern __shared__ char sm[];
    uint32_t sb = smem_u32(sm);
    int tid = threadIdx.x;
    int w = tid >> 5, lane = tid & 31;
    int g = lane >> 2, t = lane & 3;
    int bhn = blockIdx.x;
    int nck = bhn & (NCH - 1);
    int bh = bhn >> 5;
    int b = bh >> 4, h = bh & 15;
    float* dp = (float*)(sm + ST_DP);
    float decay = expf(-expf(tdecay[h]));
    if (tid < TCH) dp[tid] = powf(decay, (float)(TCH - 1 - tid));
    __syncthreads();
    size_t base = ((size_t)(b * TTT + nck * TCH)) * CC + h * KD;
    const float* gk = g_k + base;
    const float* gv = g_v + base;
#pragma unroll
    for (int it = 0; it < 4; it++) {
        int slot = tid + it * 256;
        int row = slot >> 3, uu = slot & 7;
        size_t go = (size_t)row * CC + uu * 8;
        float sc = dp[row];
        float4 f0 = *(const float4*)(gk + go);
        float4 f1 = *(const float4*)(gk + go + 4);
        f0.x *= sc; f0.y *= sc; f0.z *= sc; f0.w *= sc;
        f1.x *= sc; f1.y *= sc; f1.z *= sc; f1.w *= sc;
        cvt8_vals(f0, f1, sm, ST_KW_H, ST_KW_L, row, uu);
        cvt8_store(gv + go, sm, ST_V_H, ST_V_L, row, uu);
    }
    __syncthreads();

    int m0 = (w >> 1) * 16;          // warp M block (kk)
    int n0 = (w & 1) * 32;           // warp N block (vv)
    int at_row = ((lane >> 4) << 3) + (lane & 7);
    int at_u   = (m0 >> 3) + ((lane >> 3) & 1);
    int trow_lo = ((lane >> 3) & 1) * 8 + (lane & 7);
    int tui = lane >> 4;

    float acc[4][4];
#pragma unroll
    for (int i = 0; i < 4; i++)
#pragma unroll
        for (int q = 0; q < 4; q++) acc[i][q] = 0.f;

#pragma unroll
    for (int ks = 0; ks < 8; ks++) {
        int kk = ks * 16;
        uint32_t ah[4], al[4];
        uint32_t ad = sb + ST_KW_H + swz64(kk + at_row, at_u);
        ldsm4t(ah, ad);
        ldsm4t(al, ad + (ST_KW_L - ST_KW_H));
#pragma unroll
        for (int np = 0; np < 2; np++) {
            int nb = n0 + np * 16;
            uint32_t bd = sb + ST_V_H + swz64(kk + trow_lo, (nb >> 3) + tui);
            uint32_t bh4[4], bl4[4];
            ldsm4t(bh4, bd);
            ldsm4t(bl4, bd + (ST_V_L - ST_V_H));
#pragma unroll
            for (int sub = 0; sub < 2; sub++) {
                int ni = np * 2 + sub;
                uint32_t b0h = bh4[sub * 2], b1h = bh4[sub * 2 + 1];
                uint32_t b0l = bl4[sub * 2], b1l = bl4[sub * 2 + 1];
                mma_f16(acc[ni], ah, b0h, b1h);
                mma_f16(acc[ni], ah, b0l, b1l);
                mma_f16(acc[ni], al, b0h, b1h);
            }
        }
    }

    float* outp = g_states + (size_t)bhn * (KD * KD);
#pragma unroll
    for (int ni = 0; ni < 4; ni++) {
        int col = n0 + ni * 8 + 2 * t;
        *(float2*)&outp[(m0 + g) * KD + col]     = make_float2(acc[ni][0], acc[ni][1]);
        *(float2*)&outp[(m0 + 8 + g) * KD + col] = make_float2(acc[ni][2], acc[ni][3]);
    }
}

// ---------------- 3b) linear scan over chunks ------------------------------
__global__ void __launch_bounds__(256)
stateScan_kernel(const float* __restrict__ tdecay) {
    int bh = blockIdx.x;
    int h = bh & 15;
    int tid = threadIdx.x;
    float decay = expf(-expf(tdecay[h]));
    float ws = powf(decay, (float)TCH);
    float* base = g_states + (size_t)bh * NCH * (KD * KD) + tid * 16;
    float4 s0 = {0,0,0,0}, s1 = {0,0,0,0}, s2 = {0,0,0,0}, s3 = {0,0,0,0};
    for (int n = 0; n < NCH; n++) {
        float4* p = (float4*)(base + (size_t)n * (KD * KD));
        float4 a0 = p[0], a1 = p[1], a2 = p[2], a3 = p[3];
        p[0] = s0; p[1] = s1; p[2] = s2; p[3] = s3;
        s0.x = ws*s0.x + a0.x; s0.y = ws*s0.y + a0.y; s0.z = ws*s0.z + a0.z; s0.w = ws*s0.w + a0.w;
        s1.x = ws*s1.x + a1.x; s1.y = ws*s1.y + a1.y; s1.z = ws*s1.z + a1.z; s1.w = ws*s1.w + a1.w;
        s2.x = ws*s2.x + a2.x; s2.y = ws*s2.y + a2.y; s2.z = ws*s2.z + a2.z; s2.w = ws*s2.w + a2.w;
        s3.x = ws*s3.x + a3.x; s3.y = ws*s3.y + a3.y; s3.z = ws*s3.z + a3.z; s3.w = ws*s3.w + a3.w;
    }
}

// ---------------- 4) attention output via mma.sync + fused GN/gate ---------
#define O_R_H   0
#define O_R_L   16384
#define O_K_H   32768        // overlaid by att_h after P1
#define O_K_L   49152
#define O_ATT_H 32768
#define O_ATT_L 65536
#define O_V_H   98304
#define O_V_L   114688
#define O_S_H   131072
#define O_S_L   139264
#define O_DP    147456       // 128 floats
#define O_LW    147968       // 64 floats
#define O_LB    148224       // 64 floats
#define O_RED   148480       // 128*2 float2 = 2048
#define O_TOTAL 150528

__global__ void __launch_bounds__(256, 1)
out_mma_kernel(const float* __restrict__ tdecay, const float* __restrict__ tfa,
               const float* __restrict__ lnw, const float* __restrict__ lnb) {
    extern __shared__ char sm[];
    uint32_t sb = smem_u32(sm);
    int tid = threadIdx.x;
    int w = tid >> 5, lane = tid & 31;
    int g = lane >> 2, t = lane & 3;
    int wm = w >> 1, wn = w & 1;
    int bhn = blockIdx.x;
    int nck = bhn & (NCH - 1);
    int bh = bhn >> 5;
    int h = bh & 15, b = bh >> 4;
    float decay = expf(-expf(tdecay[h]));
    float* dp = (float*)(sm + O_DP);
    float* lws = (float*)(sm + O_LW);
    float* lbs = (float*)(sm + O_LB);
    if (tid < TCH) dp[tid] = powf(decay, (float)tid);
    if (tid < 64) { lws[tid] = lnw[h * 64 + tid]; lbs[tid] = lnb[h * 64 + tid]; }
    float uf = tfa[h];
    size_t base = ((size_t)(b * TTT + nck * TCH)) * CC + h * KD;

    {
        const float* gr = g_r + base;
        const float* gk = g_k + base;
        const float* gv = g_v + base;
#pragma unroll
        for (int it = 0; it < 4; it++) {
            int slot = tid + it * 256;
            int row = slot >> 3, uu = slot & 7;
            size_t go = (size_t)row * CC + uu * 8;
            cvt8_store(gr + go, sm, O_R_H, O_R_L, row, uu);
            cvt8_store(gk + go, sm, O_K_H, O_K_L, row, uu);
            cvt8_store(gv + go, sm, O_V_H, O_V_L, row, uu);
        }
        const float* sp = g_states + ((size_t)bh * NCH + nck) * (KD * KD);
#pragma unroll
        for (int it = 0; it < 2; it++) {
            int slot = tid + it * 256;
            int row = slot >> 3, uu = slot & 7;
            cvt8_store(sp + (size_t)row * KD + uu * 8, sm, O_S_H, O_S_L, row, uu);
        }
    }
    __syncthreads();

    int arow = lane & 15;
    int akof = (lane >> 4) << 3;
    int brow = ((lane >> 4) << 3) + (lane & 7);
    int bkof = ((lane >> 3) & 1) << 3;

    // ---- P1: att = (r . k^T) * w_mat ----
    float acc1[2][8][4];
#pragma unroll
    for (int mi = 0; mi < 2; mi++)
#pragma unroll
        for (int ni = 0; ni < 8; ni++)
#pragma unroll
            for (int q = 0; q < 4; q++) acc1[mi][ni][q] = 0.f;
#pragma unroll
    for (int ks = 0; ks < 4; ks++) {
        int kk = ks * 16;
        int uA = (kk + akof) >> 3;
        uint32_t ah[2][4], al[2][4];
#pragma unroll
        for (int mi = 0; mi < 2; mi++) {
            uint32_t ad = sb + O_R_H + swz64(wm * 32 + mi * 16 + arow, uA);
            ldsm4(ah[mi], ad);
            ldsm4(al[mi], ad + (O_R_L - O_R_H));
        }
        int uB = (kk + bkof) >> 3;
#pragma unroll
        for (int np = 0; np < 4; np++) {
            uint32_t bd = sb + O_K_H + swz64(wn * 64 + np * 16 + brow, uB);
            uint32_t bh4[4], bl4[4];
            ldsm4(bh4, bd);
            ldsm4(bl4, bd + (O_K_L - O_K_H));
#pragma unroll
            for (int sub = 0; sub < 2; sub++) {
                int ni = np * 2 + sub;
                uint32_t b0h = bh4[sub * 2], b1h = bh4[sub * 2 + 1];
                uint32_t b0l = bl4[sub * 2], b1l = bl4[sub * 2 + 1];
#pragma unroll
                for (int mi = 0; mi < 2; mi++) {
                    mma_f16(acc1[mi][ni], ah[mi], b0h, b1h);
                    mma_f16(acc1[mi][ni], ah[mi], b0l, b1l);
                    mma_f16(acc1[mi][ni], al[mi], b0h, b1h);
                }
            }
        }
    }
    __syncthreads();

    // apply w_mat, store att hi/lo (256B rows, swzA)
#pragma unroll
    for (int mi = 0; mi < 2; mi++) {
        int r0 = wm * 32 + mi * 16 + g;
        int r1 = r0 + 8;
#pragma unroll
        for (int ni = 0; ni < 8; ni++) {
            int cc = wn * 64 + ni * 8 + 2 * t;
            int d;
            d = r0 - cc;     float w00 = (d > 0) ? dp[d - 1] : ((d == 0) ? uf : 0.f);
            d = r0 - cc - 1; float w01 = (d > 0) ? dp[d - 1] : ((d == 0) ? uf : 0.f);
            d = r1 - cc;     float w10 = (d > 0) ? dp[d - 1] : ((d == 0) ? uf : 0.f);
            d = r1 - cc - 1; float w11 = (d > 0) ? dp[d - 1] : ((d == 0) ? uf : 0.f);
            float a0 = acc1[mi][ni][0] * w00, a1 = acc1[mi][ni][1] * w01;
            float a2 = acc1[mi][ni][2] * w10, a3 = acc1[mi][ni][3] * w11;
            uint32_t o0 = swzA(r0, cc >> 3) + (cc & 7) * 2;
            uint32_t o1 = swzA(r1, cc >> 3) + (cc & 7) * 2;
            uint32_t hA = h2pack(a0, a1), hB = h2pack(a2, a3);
            *(uint32_t*)(sm + O_ATT_H + o0) = hA;
            *(uint32_t*)(sm + O_ATT_H + o1) = hB;
            __half2 hAv = *(__half2*)&hA;
            __half2 hBv = *(__half2*)&hB;
            *(uint32_t*)(sm + O_ATT_L + o0) =
                h2pack(a0 - __half2float(hAv.x), a1 - __half2float(hAv.y));
            *(uint32_t*)(sm + O_ATT_L + o1) =
                h2pack(a2 - __half2float(hBv.x), a3 - __half2float(hBv.y));
        }
    }
    __syncthreads();

    // ---- P2: out = att @ v + (r @ s) * dp[row] ----
    float acc2[2][4][4], acc3[2][4][4];
#pragma unroll
    for (int mi = 0; mi < 2; mi++)
#pragma unroll
        for (int ni = 0; ni < 4; ni++)
#pragma unroll
            for (int q = 0; q < 4; q++) { acc2[mi][ni][q] = 0.f; acc3[mi][ni][q] = 0.f; }

    int trow_lo = ((lane >> 3) & 1) * 8 + (lane & 7);
    int tui = lane >> 4;
#pragma unroll
    for (int ks = 0; ks < 8; ks++) {
        int kk = ks * 16;
        int uA = (kk + akof) >> 3;
        uint32_t ah[2][4], al[2][4];
#pragma unroll
        for (int mi = 0; mi < 2; mi++) {
            uint32_t ad = sb + O_ATT_H + swzA(wm * 32 + mi * 16 + arow, uA);
            ldsm4(ah[mi], ad);
            ldsm4(al[mi], ad + (O_ATT_L - O_ATT_H));
        }
#pragma unroll
        for (int np = 0; np < 2; np++) {
            int nb = wn * 32 + np * 16;
            uint32_t bd = sb + O_V_H + swz64(kk + trow_lo, (nb >> 3) + tui);
            uint32_t bh4[4], bl4[4];
            ldsm4t(bh4, bd);
            ldsm4t(bl4, bd + (O_V_L - O_V_H));
#pragma unroll
            for (int sub = 0; sub < 2; sub++) {
                int ni = np * 2 + sub;
                uint32_t b0h = bh4[sub * 2], b1h = bh4[sub * 2 + 1];
                uint32_t b0l = bl4[sub * 2], b1l = bl4[sub * 2 + 1];
#pragma unroll
                for (int mi = 0; mi < 2; mi++) {
                    mma_f16(acc2[mi][ni], ah[mi], b0h, b1h);
                    mma_f16(acc2[mi][ni], ah[mi], b0l, b1l);
                    mma_f16(acc2[mi][ni], al[mi], b0h, b1h);
                }
            }
        }
    }
#pragma unroll
    for (int ks = 0; ks < 4; ks++) {
        int kk = ks * 16;
        int uA = (kk + akof) >> 3;
        uint32_t ah[2][4], al[2][4];
#pragma unroll
        for (int mi = 0; mi < 2; mi++) {
            uint32_t ad = sb + O_R_H + swz64(wm * 32 + mi * 16 + arow, uA);
            ldsm4(ah[mi], ad);
            ldsm4(al[mi], ad + (O_R_L - O_R_H));
        }
#pragma unroll
        for (int np = 0; np < 2; np++) {
            int nb = wn * 32 + np * 16;
            uint32_t bd = sb + O_S_H + swz64(kk + trow_lo, (nb >> 3) + tui);
            uint32_t bh4[4], bl4[4];
            ldsm4t(bh4, bd);
            ldsm4t(bl4, bd + (O_S_L - O_S_H));
#pragma unroll
            for (int sub = 0; sub < 2; sub++) {
                int ni = np * 2 + sub;
                uint32_t b0h = bh4[sub * 2], b1h = bh4[sub * 2 + 1];
                uint32_t b0l = bl4[sub * 2], b1l = bl4[sub * 2 + 1];
#pragma unroll
                for (int mi = 0; mi < 2; mi++) {
                    mma_f16(acc3[mi][ni], ah[mi], b0h, b1h);
                    mma_f16(acc3[mi][ni], ah[mi], b0l, b1l);
                    mma_f16(acc3[mi][ni], al[mi], b0h, b1h);
                }
            }
        }
    }

    // ---- epilogue: y = out/8, GroupNorm over 64 ch, *lnw+lnb, *silu(g) ----
    float2* red = (float2*)(sm + O_RED);
#pragma unroll
    for (int mi = 0; mi < 2; mi++) {
        int r0 = wm * 32 + mi * 16 + g, r1 = r0 + 8;
        float d0 = dp[r0], d1 = dp[r1];
        float sA = 0.f, qA = 0.f, sB = 0.f, qB = 0.f;
#pragma unroll
        for (int ni = 0; ni < 4; ni++) {
            float y0 = (acc2[mi][ni][0] + d0 * acc3[mi][ni][0]) * 0.125f;
            float y1 = (acc2[mi][ni][1] + d0 * acc3[mi][ni][1]) * 0.125f;
            float y2 = (acc2[mi][ni][2] + d1 * acc3[mi][ni][2]) * 0.125f;
            float y3 = (acc2[mi][ni][3] + d1 * acc3[mi][ni][3]) * 0.125f;
            acc2[mi][ni][0] = y0; acc2[mi][ni][1] = y1;
            acc2[mi][ni][2] = y2; acc2[mi][ni][3] = y3;
            sA += y0 + y1; qA += y0 * y0 + y1 * y1;
            sB += y2 + y3; qB += y2 * y2 + y3 * y3;
        }
#pragma unroll
        for (int o = 1; o < 4; o <<= 1) {
            sA += __shfl_xor_sync(0xffffffffu, sA, o);
            qA += __shfl_xor_sync(0xffffffffu, qA, o);
            sB += __shfl_xor_sync(0xffffffffu, sB, o);
            qB += __shfl_xor_sync(0xffffffffu, qB, o);
        }
        if (t == 0) {
            red[r0 * 2 + wn] = make_float2(sA, qA);
            red[r1 * 2 + wn] = make_float2(sB, qB);
        }
    }
    __syncthreads();
#pragma unroll
    for (int mi = 0; mi < 2; mi++) {
        int r0 = wm * 32 + mi * 16 + g, r1 = r0 + 8;
        float2 pa = red[r0 * 2], pb = red[r0 * 2 + 1];
        float mu0 = (pa.x + pb.x) * (1.f / 64.f);
        float var0 = (pa.y + pb.y) * (1.f / 64.f) - mu0 * mu0;
        float inv0 = rsqrtf(var0 + 1e-5f);
        pa = red[r1 * 2]; pb = red[r1 * 2 + 1];
        float mu1 = (pa.x + pb.x) * (1.f / 64.f);
        float var1 = (pa.y + pb.y) * (1.f / 64.f) - mu1 * mu1;
        float inv1 = rsqrtf(var1 + 1e-5f);
#pragma unroll
        for (int ni = 0; ni < 4; ni++) {
            int cc = wn * 32 + ni * 8 + 2 * t;
            float lw0 = lws[cc], lw1 = lws[cc + 1];
            float lb0 = lbs[cc], lb1 = lbs[cc + 1];
            float2 gA = *(const float2*)(g_g + base + (size_t)r0 * CC + cc);
            float2 gB = *(const float2*)(g_g + base + (size_t)r1 * CC + cc);
            float s0g = gA.x / (1.f + expf(-gA.x));
            float s1g = gA.y / (1.f + expf(-gA.y));
            float s2g = gB.x / (1.f + expf(-gB.x));
            float s3g = gB.y / (1.f + expf(-gB.y));
            float z0 = ((acc2[mi][ni][0] - mu0) * inv0 * lw0 + lb0) * s0g;
            float z1 = ((acc2[mi][ni][1] - mu0) * inv0 * lw1 + lb1) * s1g;
            float z2 = ((acc2[mi][ni][2] - mu1) * inv1 * lw0 + lb0) * s2g;
            float z3 = ((acc2[mi][ni][3] - mu1) * inv1 * lw1 + lb1) * s3g;
            size_t i0 = base + (size_t)r0 * CC + cc;
            size_t i1 = base + (size_t)r1 * CC + cc;
            *(uint32_t*)(g_z + i0) = h2pack(z0, z1);
            *(uint32_t*)(g_z + i1) = h2pack(z2, z3);
        }
    }
}

// ---------------- launch ---------------------------------------------------
extern "C" void kernel_launch(void* const* d_in, const int* in_sizes, int n_in,
                              void* d_out, int out_size) {
    const float* xq     = (const float*)d_in[0];
    const float* tmk    = (const float*)d_in[1];
    const float* tmv    = (const float*)d_in[2];
    const float* tmr    = (const float*)d_in[3];
    const float* tmg    = (const float*)d_in[4];
    const float* tdecay = (const float*)d_in[5];
    const float* tfa    = (const float*)d_in[6];
    const float* Wr     = (const float*)d_in[7];
    const float* Wk     = (const float*)d_in[8];
    const float* Wv     = (const float*)d_in[9];
    const float* Wg     = (const float*)d_in[10];
    const float* Wo     = (const float*)d_in[11];
    const float* lnw    = (const float*)d_in[12];
    const float* lnb    = (const float*)d_in[13];
    float* out = (float*)d_out;

    __half *pxr, *pxk, *pxv, *pxg, *pz;
    __half *pwr, *pwk, *pwv, *pwg, *pwo;
    float *pr, *pk, *pv, *pg;
    cudaGetSymbolAddress((void**)&pxr, g_xr);
    cudaGetSymbolAddress((void**)&pxk, g_xk);
    cudaGetSymbolAddress((void**)&pxv, g_xv);
    cudaGetSymbolAddress((void**)&pxg, g_xg);
    cudaGetSymbolAddress((void**)&pz,  g_z);
    cudaGetSymbolAddress((void**)&pwr, g_wr); cudaGetSymbolAddress((void**)&pwk, g_wk);
    cudaGetSymbolAddress((void**)&pwv, g_wv); cudaGetSymbolAddress((void**)&pwg, g_wg);
    cudaGetSymbolAddress((void**)&pwo, g_wo);
    cudaGetSymbolAddress((void**)&pr, g_r); cudaGetSymbolAddress((void**)&pk, g_k);
    cudaGetSymbolAddress((void**)&pv, g_v); cudaGetSymbolAddress((void**)&pg, g_g);

    wsplit5_kernel<<<dim3(CC * CC / 256, 5), 256>>>(
        Wr, Wk, Wv, Wg, Wo, pwr, pwk, pwv, pwg, pwo);

    mix_kernel<<<MM * CC / 1024, 256>>>(xq, tmk, tmv, tmr, tmg);

    cudaFuncSetAttribute(gemm_mma, cudaFuncAttributeMaxDynamicSharedMemorySize,
                         GSM_TOTAL);
    gemm_mma<<<dim3(CC / 128, MM / 128, 4), 256, GSM_TOTAL>>>(
        pxr, pwr, pr,
        pxk, pwk, pk,
        pxv, pwv, pv,
        pxg, pwg, pg);

    cudaFuncSetAttribute(stateA_kernel, cudaFuncAttributeMaxDynamicSharedMemorySize,
                         ST_TOTAL);
    stateA_kernel<<<BB * HH * NCH, 256, ST_TOTAL>>>(tdecay);
    stateScan_kernel<<<BB * HH, 256>>>(tdecay);

    cudaFuncSetAttribute(out_mma_kernel, cudaFuncAttributeMaxDynamicSharedMemorySize,
                         O_TOTAL);
    out_mma_kernel<<<BB * HH * NCH, 256, O_TOTAL>>>(tdecay, tfa, lnw, lnb);

    gemm_mma<<<dim3(CC / 128, MM / 128, 1), 256, GSM_TOTAL>>>(
        pz, pwo, out,
        pz, pwo, out,
        pz, pwo, out,
        pz, pwo, out);
}

// round 15
// speedup vs baseline: 1.4569x; 1.4569x over previous
#include <cuda_runtime.h>
#include <cuda_fp16.h>
#include <stdint.h>
#include <math.h>

// Problem constants
#define BB   4
#define TTT  4096
#define CC   1024
#define HH   16
#define KD   64          // head dim
#define TCH  128         // chunk length
#define NCH  32          // chunks
#define MM   (BB*TTT)    // 16384 rows

// ---------------- scratch (device globals; no allocation allowed) ----------
__device__ __half g_xr[MM*CC];
__device__ __half g_xk[MM*CC];
__device__ __half g_xv[MM*CC];
__device__ __half g_xg[MM*CC];
__device__ __half g_z [MM*CC];
__device__ __half g_wr[CC*CC];
__device__ __half g_wk[CC*CC];
__device__ __half g_wv[CC*CC];
__device__ __half g_wg[CC*CC];
__device__ __half g_wo[CC*CC];
__device__ float g_r [MM*CC];
__device__ float g_k [MM*CC];
__device__ float g_v [MM*CC];
__device__ float g_g [MM*CC];
__device__ float g_states[BB*HH*NCH*KD*KD];

// ---------------- helpers ---------------------------------------------------
__device__ __forceinline__ void mma_f16(float* c, const uint32_t* a,
                                        uint32_t b0, uint32_t b1) {
    asm volatile(
        "mma.sync.aligned.m16n8k16.row.col.f32.f16.f16.f32 "
        "{%0,%1,%2,%3}, {%4,%5,%6,%7}, {%8,%9}, {%0,%1,%2,%3};"
        : "+f"(c[0]), "+f"(c[1]), "+f"(c[2]), "+f"(c[3])
        : "r"(a[0]), "r"(a[1]), "r"(a[2]), "r"(a[3]), "r"(b0), "r"(b1));
}

__device__ __forceinline__ uint32_t smem_u32(const void* p) {
    uint32_t a;
    asm("{ .reg .u64 t; cvta.to.shared.u64 t, %1; cvt.u32.u64 %0, t; }"
        : "=r"(a) : "l"(p));
    return a;
}
__device__ __forceinline__ void cp16(uint32_t saddr, const void* g) {
    asm volatile("cp.async.cg.shared.global [%0], [%1], 16;" :: "r"(saddr), "l"(g));
}
__device__ __forceinline__ void cp_commit() {
    asm volatile("cp.async.commit_group;");
}
__device__ __forceinline__ void cp_wait1() {
    asm volatile("cp.async.wait_group 1;");
}
__device__ __forceinline__ void ldsm4(uint32_t* r, uint32_t addr) {
    asm volatile("ldmatrix.sync.aligned.m8n8.x4.shared.b16 {%0,%1,%2,%3}, [%4];"
                 : "=r"(r[0]), "=r"(r[1]), "=r"(r[2]), "=r"(r[3]) : "r"(addr));
}
__device__ __forceinline__ void ldsm4t(uint32_t* r, uint32_t addr) {
    asm volatile("ldmatrix.sync.aligned.m8n8.x4.trans.shared.b16 {%0,%1,%2,%3}, [%4];"
                 : "=r"(r[0]), "=r"(r[1]), "=r"(r[2]), "=r"(r[3]) : "r"(addr));
}

__device__ __forceinline__ uint32_t h2pack(float a, float b) {
    __half2 h(__float2half_rn(a), __float2half_rn(b));
    return *(uint32_t*)&h;
}

// swizzled byte offset within a 128-row x 64B tile: row r, 16B-unit u (0..3)
__device__ __forceinline__ uint32_t swz(int r, int u) {
    return (uint32_t)(r * 64 + ((u ^ ((r >> 1) & 3)) << 4));
}
// 128B rows (64 fp16): unit u 0..7
__device__ __forceinline__ uint32_t swz64(int r, int u) {
    return (uint32_t)(r * 128 + ((u ^ (r & 7)) << 4));
}
// 256B rows (128 fp16): unit u 0..15
__device__ __forceinline__ uint32_t swzA(int r, int u) {
    int phys = (u & 8) | ((u ^ (r & 7)) & 7);
    return (uint32_t)(r * 256 + phys * 16);
}

// ---------------- 0) weight convert fp32 -> fp16 (all 5 fused) -------------
__global__ void wsplit5_kernel(const float* __restrict__ W0, const float* __restrict__ W1,
                               const float* __restrict__ W2, const float* __restrict__ W3,
                               const float* __restrict__ W4,
                               __half* __restrict__ H0, __half* __restrict__ H1,
                               __half* __restrict__ H2, __half* __restrict__ H3,
                               __half* __restrict__ H4) {
    int i = blockIdx.x * blockDim.x + threadIdx.x;
    const float* W; __half* Hh;
    switch (blockIdx.y) {
        case 0: W = W0; Hh = H0; break;
        case 1: W = W1; Hh = H1; break;
        case 2: W = W2; Hh = H2; break;
        case 3: W = W3; Hh = H3; break;
        default: W = W4; Hh = H4; break;
    }
    Hh[i] = __float2half_rn(W[i]);
}

// ---------------- 1) time-shift mixing -> fp16 (float4 vectorized) ---------
__device__ __forceinline__ void mix4_store(const float* __restrict__ tm, int c,
                                           float4 xc, float4 xp,
                                           __half* __restrict__ H, int idx) {
    float4 m = *(const float4*)(tm + c);
    float y0 = xc.x * m.x + xp.x * (1.f - m.x);
    float y1 = xc.y * m.y + xp.y * (1.f - m.y);
    float y2 = xc.z * m.z + xp.z * (1.f - m.z);
    float y3 = xc.w * m.w + xp.w * (1.f - m.w);
    uint2 hv = make_uint2(h2pack(y0, y1), h2pack(y2, y3));
    *(uint2*)(H + idx) = hv;
}

__global__ void mix_kernel(const float* __restrict__ x,
                           const float* __restrict__ tmk,
                           const float* __restrict__ tmv,
                           const float* __restrict__ tmr,
                           const float* __restrict__ tmg) {
    int idx = (blockIdx.x * blockDim.x + threadIdx.x) * 4;
    int c = idx & (CC - 1);
    int t = (idx >> 10) & (TTT - 1);
    float4 xc = *(const float4*)(x + idx);
    float4 xp = t ? *(const float4*)(x + idx - CC) : make_float4(0.f, 0.f, 0.f, 0.f);
    mix4_store(tmr, c, xc, xp, g_xr, idx);
    mix4_store(tmk, c, xc, xp, g_xk, idx);
    mix4_store(tmv, c, xc, xp, g_xv, idx);
    mix4_store(tmg, c, xc, xp, g_xg, idx);
}

// ---------------- 2) mma.sync GEMM: C = A @ W^T (fp16, K-chunk 32) ---------
// CTA tile 128x128, 8 warps (warp tile 32x64), K-chunk 32.
// 3-stage cp.async, 48KB smem, 2 CTAs/SM.  (Round-12 proven config.)
#define KCH     32
#define TILE_B  8192                     // 128 rows x 64B
#define BUF_B   (2*TILE_B)               // A, B
#define GSM_TOTAL (3*BUF_B)              // 49152 B
#define NKC     (CC/KCH)                 // 32 chunks

__global__ void __launch_bounds__(256, 2)
gemm_mma(const __half* __restrict__ A0, const __half* __restrict__ B0,
         float* __restrict__ C0,
         const __half* __restrict__ A1, const __half* __restrict__ B1,
         float* __restrict__ C1,
         const __half* __restrict__ A2, const __half* __restrict__ B2,
         float* __restrict__ C2,
         const __half* __restrict__ A3, const __half* __restrict__ B3,
         float* __restrict__ C3) {
    extern __shared__ char dsm[];
    uint32_t sbase = smem_u32(dsm);
    int tid = threadIdx.x;
    int w   = tid >> 5;
    int lane = tid & 31;
    int g = lane >> 2;
    int t = lane & 3;
    int n0 = blockIdx.x * 128;
    int m0 = blockIdx.y * 128;
    int m0w = (w >> 1) * 32;
    int n0w = (w & 1) * 64;

    const __half *Aa, *Bw; float* C;
    switch (blockIdx.z) {
        case 0: Aa = A0; Bw = B0; C = C0; break;
        case 1: Aa = A1; Bw = B1; C = C1; break;
        case 2: Aa = A2; Bw = B2; C = C2; break;
        default: Aa = A3; Bw = B3; C = C3; break;
    }
    const __half* sA = Aa + (size_t)m0 * CC;
    const __half* sB = Bw + (size_t)n0 * CC;

    int r0 = tid >> 2, u = tid & 3;
    size_t go0 = (size_t)r0 * CC + u * 8;
    size_t go1 = go0 + (size_t)64 * CC;
    uint32_t so0 = swz(r0, u);
    uint32_t so1 = so0 + 64 * 64;

    int arow = lane & 15;
    int akof = (lane >> 4) << 3;
    int brow = ((lane >> 4) << 3) + (lane & 7);
    int bkof = ((lane >> 3) & 1) << 3;
    int rowA0 = m0w + arow, rowA1 = m0w + 16 + arow;

    float acc[2][8][4];
#pragma unroll
    for (int mi = 0; mi < 2; mi++)
#pragma unroll
        for (int ni = 0; ni < 8; ni++)
#pragma unroll
            for (int q = 0; q < 4; q++) acc[mi][ni][q] = 0.f;

    auto issue = [&](int chunk) {
        int k0 = chunk * KCH;
        uint32_t b = sbase + (uint32_t)((chunk % 3) * BUF_B);
        cp16(b + 0*TILE_B + so0, sA + go0 + k0); cp16(b + 0*TILE_B + so1, sA + go1 + k0);
        cp16(b + 1*TILE_B + so0, sB + go0 + k0); cp16(b + 1*TILE_B + so1, sB + go1 + k0);
        cp_commit();
    };

    issue(0);
    issue(1);

    for (int c = 0; c < NKC; ++c) {
        cp_wait1();
        __syncthreads();
        if (c + 2 < NKC) issue(c + 2);

        uint32_t sb = sbase + (uint32_t)((c % 3) * BUF_B);
        uint32_t tA = sb;
        uint32_t tB = sb + TILE_B;
#pragma unroll
        for (int ks = 0; ks < 2; ++ks) {
            int kk = ks * 16;
            int uA = (kk + akof) >> 3;
            uint32_t ah[2][4];
            {
                ldsm4(ah[0], tA + swz(rowA0, uA));
                ldsm4(ah[1], tA + swz(rowA1, uA));
            }
            int uB = (kk + bkof) >> 3;
#pragma unroll
            for (int np = 0; np < 4; np++) {
                uint32_t b4[4];
                ldsm4(b4, tB + swz(n0w + np * 16 + brow, uB));
#pragma unroll
                for (int sub = 0; sub < 2; sub++) {
                    int ni = np * 2 + sub;
                    uint32_t b0 = b4[sub * 2], b1 = b4[sub * 2 + 1];
#pragma unroll
                    for (int mi = 0; mi < 2; mi++)
                        mma_f16(acc[mi][ni], ah[mi], b0, b1);
                }
            }
        }
    }

#pragma unroll
    for (int mi = 0; mi < 2; mi++) {
        int r = m0 + m0w + mi * 16 + g;
#pragma unroll
        for (int ni = 0; ni < 8; ni++) {
            int col = n0 + n0w + ni * 8 + 2 * t;
            *(float2*)&C[(size_t)r * CC + col] =
                make_float2(acc[mi][ni][0], acc[mi][ni][1]);
            *(float2*)&C[(size_t)(r + 8) * CC + col] =
                make_float2(acc[mi][ni][2], acc[mi][ni][3]);
        }
    }
}

// ---------------- shared convert helper: 8 fp32 -> fp16 hi/lo swizzled -----
__device__ __forceinline__ void cvt8_vals(float4 f0, float4 f1, char* smbase,
                                          uint32_t offH, uint32_t offL,
                                          int row, int uu) {
    uint4 hi = make_uint4(h2pack(f0.x, f0.y), h2pack(f0.z, f0.w),
                          h2pack(f1.x, f1.y), h2pack(f1.z, f1.w));
    uint32_t sw = swz64(row, uu);
    *(uint4*)(smbase + offH + sw) = hi;
    __half2* hp = (__half2*)&hi;
    uint4 lo = make_uint4(
        h2pack(f0.x - __half2float(hp[0].x), f0.y - __half2float(hp[0].y)),
        h2pack(f0.z - __half2float(hp[1].x), f0.w - __half2float(hp[1].y)),
        h2pack(f1.x - __half2float(hp[2].x), f1.y - __half2float(hp[2].y)),
        h2pack(f1.z - __half2float(hp[3].x), f1.w - __half2float(hp[3].y)));
    *(uint4*)(smbase + offL + sw) = lo;
}
__device__ __forceinline__ void cvt8_store(const float* src, char* smbase,
                                           uint32_t offH, uint32_t offL,
                                           int row, int uu) {
    float4 f0 = *(const float4*)(src);
    float4 f1 = *(const float4*)(src + 4);
    cvt8_vals(f0, f1, smbase, offH, offL, row, uu);
}

// ---------------- 3a) per-chunk state contributions via mma.sync -----------
// A_n[kk][vv] = sum_j (k[j][kk]*dp[j]) * v[j][vv] : GEMM M=64,N=64,K=128.
#define ST_KW_H 0
#define ST_KW_L 16384
#define ST_V_H  32768
#define ST_V_L  49152
#define ST_DP   65536        // 128 floats
#define ST_TOTAL 66048

__global__ void __launch_bounds__(256, 2)
stateA_kernel(const float* __restrict__ tdecay) {
    extern __shared__ char sm[];
    uint32_t sb = smem_u32(sm);
    int tid = threadIdx.x;
    int w = tid >> 5, lane = tid & 31;
    int g = lane >> 2, t = lane & 3;
    int bhn = blockIdx.x;
    int nck = bhn & (NCH - 1);
    int bh = bhn >> 5;
    int b = bh >> 4, h = bh & 15;
    float* dp = (float*)(sm + ST_DP);
    float decay = expf(-expf(tdecay[h]));
    if (tid < TCH) dp[tid] = powf(decay, (float)(TCH - 1 - tid));
    __syncthreads();
    size_t base = ((size_t)(b * TTT + nck * TCH)) * CC + h * KD;
    const float* gk = g_k + base;
    const float* gv = g_v + base;
#pragma unroll
    for (int it = 0; it < 4; it++) {
        int slot = tid + it * 256;
        int row = slot >> 3, uu = slot & 7;
        size_t go = (size_t)row * CC + uu * 8;
        float sc = dp[row];
        float4 f0 = *(const float4*)(gk + go);
        float4 f1 = *(const float4*)(gk + go + 4);
        f0.x *= sc; f0.y *= sc; f0.z *= sc; f0.w *= sc;
        f1.x *= sc; f1.y *= sc; f1.z *= sc; f1.w *= sc;
        cvt8_vals(f0, f1, sm, ST_KW_H, ST_KW_L, row, uu);
        cvt8_store(gv + go, sm, ST_V_H, ST_V_L, row, uu);
    }
    __syncthreads();

    int m0 = (w >> 1) * 16;          // warp M block (kk)
    int n0 = (w & 1) * 32;           // warp N block (vv)
    int at_row = ((lane >> 4) << 3) + (lane & 7);
    int at_u   = (m0 >> 3) + ((lane >> 3) & 1);
    int trow_lo = ((lane >> 3) & 1) * 8 + (lane & 7);
    int tui = lane >> 4;

    float acc[4][4];
#pragma unroll
    for (int i = 0; i < 4; i++)
#pragma unroll
        for (int q = 0; q < 4; q++) acc[i][q] = 0.f;

#pragma unroll
    for (int ks = 0; ks < 8; ks++) {
        int kk = ks * 16;
        uint32_t ah[4], al[4];
        uint32_t ad = sb + ST_KW_H + swz64(kk + at_row, at_u);
        ldsm4t(ah, ad);
        ldsm4t(al, ad + (ST_KW_L - ST_KW_H));
#pragma unroll
        for (int np = 0; np < 2; np++) {
            int nb = n0 + np * 16;
            uint32_t bd = sb + ST_V_H + swz64(kk + trow_lo, (nb >> 3) + tui);
            uint32_t bh4[4], bl4[4];
            ldsm4t(bh4, bd);
            ldsm4t(bl4, bd + (ST_V_L - ST_V_H));
#pragma unroll
            for (int sub = 0; sub < 2; sub++) {
                int ni = np * 2 + sub;
                uint32_t b0h = bh4[sub * 2], b1h = bh4[sub * 2 + 1];
                uint32_t b0l = bl4[sub * 2], b1l = bl4[sub * 2 + 1];
                mma_f16(acc[ni], ah, b0h, b1h);
                mma_f16(acc[ni], ah, b0l, b1l);
                mma_f16(acc[ni], al, b0h, b1h);
            }
        }
    }

    float* outp = g_states + (size_t)bhn * (KD * KD);
#pragma unroll
    for (int ni = 0; ni < 4; ni++) {
        int col = n0 + ni * 8 + 2 * t;
        *(float2*)&outp[(m0 + g) * KD + col]     = make_float2(acc[ni][0], acc[ni][1]);
        *(float2*)&outp[(m0 + 8 + g) * KD + col] = make_float2(acc[ni][2], acc[ni][3]);
    }
}

// ---------------- 3b) linear scan over chunks ------------------------------
__global__ void __launch_bounds__(256)
stateScan_kernel(const float* __restrict__ tdecay) {
    int bh = blockIdx.x;
    int h = bh & 15;
    int tid = threadIdx.x;
    float decay = expf(-expf(tdecay[h]));
    float ws = powf(decay, (float)TCH);
    float* base = g_states + (size_t)bh * NCH * (KD * KD) + tid * 16;
    float4 s0 = {0,0,0,0}, s1 = {0,0,0,0}, s2 = {0,0,0,0}, s3 = {0,0,0,0};
    for (int n = 0; n < NCH; n++) {
        float4* p = (float4*)(base + (size_t)n * (KD * KD));
        float4 a0 = p[0], a1 = p[1], a2 = p[2], a3 = p[3];
        p[0] = s0; p[1] = s1; p[2] = s2; p[3] = s3;
        s0.x = ws*s0.x + a0.x; s0.y = ws*s0.y + a0.y; s0.z = ws*s0.z + a0.z; s0.w = ws*s0.w + a0.w;
        s1.x = ws*s1.x + a1.x; s1.y = ws*s1.y + a1.y; s1.z = ws*s1.z + a1.z; s1.w = ws*s1.w + a1.w;
        s2.x = ws*s2.x + a2.x; s2.y = ws*s2.y + a2.y; s2.z = ws*s2.z + a2.z; s2.w = ws*s2.w + a2.w;
        s3.x = ws*s3.x + a3.x; s3.y = ws*s3.y + a3.y; s3.z = ws*s3.z + a3.z; s3.w = ws*s3.w + a3.w;
    }
}

// ---------------- 4) attention output via mma.sync + fused GN/gate ---------
#define O_R_H   0
#define O_R_L   16384
#define O_K_H   32768        // overlaid by att_h after P1
#define O_K_L   49152
#define O_ATT_H 32768
#define O_ATT_L 65536
#define O_V_H   98304
#define O_V_L   114688
#define O_S_H   131072
#define O_S_L   139264
#define O_DP    147456       // 128 floats
#define O_LW    147968       // 64 floats
#define O_LB    148224       // 64 floats
#define O_RED   148480       // 128*2 float2 = 2048
#define O_TOTAL 150528

__global__ void __launch_bounds__(256, 1)
out_mma_kernel(const float* __restrict__ tdecay, const float* __restrict__ tfa,
               const float* __restrict__ lnw, const float* __restrict__ lnb) {
    extern __shared__ char sm[];
    uint32_t sb = smem_u32(sm);
    int tid = threadIdx.x;
    int w = tid >> 5, lane = tid & 31;
    int g = lane >> 2, t = lane & 3;
    int wm = w >> 1, wn = w & 1;
    int bhn = blockIdx.x;
    int nck = bhn & (NCH - 1);
    int bh = bhn >> 5;
    int h = bh & 15, b = bh >> 4;
    float decay = expf(-expf(tdecay[h]));
    float* dp = (float*)(sm + O_DP);
    float* lws = (float*)(sm + O_LW);
    float* lbs = (float*)(sm + O_LB);
    if (tid < TCH) dp[tid] = powf(decay, (float)tid);
    if (tid < 64) { lws[tid] = lnw[h * 64 + tid]; lbs[tid] = lnb[h * 64 + tid]; }
    float uf = tfa[h];
    size_t base = ((size_t)(b * TTT + nck * TCH)) * CC + h * KD;

    {
        const float* gr = g_r + base;
        const float* gk = g_k + base;
        const float* gv = g_v + base;
#pragma unroll
        for (int it = 0; it < 4; it++) {
            int slot = tid + it * 256;
            int row = slot >> 3, uu = slot & 7;
            size_t go = (size_t)row * CC + uu * 8;
            cvt8_store(gr + go, sm, O_R_H, O_R_L, row, uu);
            cvt8_store(gk + go, sm, O_K_H, O_K_L, row, uu);
            cvt8_store(gv + go, sm, O_V_H, O_V_L, row, uu);
        }
        const float* sp = g_states + ((size_t)bh * NCH + nck) * (KD * KD);
#pragma unroll
        for (int it = 0; it < 2; it++) {
            int slot = tid + it * 256;
            int row = slot >> 3, uu = slot & 7;
            cvt8_store(sp + (size_t)row * KD + uu * 8, sm, O_S_H, O_S_L, row, uu);
        }
    }
    __syncthreads();

    int arow = lane & 15;
    int akof = (lane >> 4) << 3;
    int brow = ((lane >> 4) << 3) + (lane & 7);
    int bkof = ((lane >> 3) & 1) << 3;

    // ---- P1: att = (r . k^T) * w_mat ----
    float acc1[2][8][4];
#pragma unroll
    for (int mi = 0; mi < 2; mi++)
#pragma unroll
        for (int ni = 0; ni < 8; ni++)
#pragma unroll
            for (int q = 0; q < 4; q++) acc1[mi][ni][q] = 0.f;
#pragma unroll
    for (int ks = 0; ks < 4; ks++) {
        int kk = ks * 16;
        int uA = (kk + akof) >> 3;
        uint32_t ah[2][4], al[2][4];
#pragma unroll
        for (int mi = 0; mi < 2; mi++) {
            uint32_t ad = sb + O_R_H + swz64(wm * 32 + mi * 16 + arow, uA);
            ldsm4(ah[mi], ad);
            ldsm4(al[mi], ad + (O_R_L - O_R_H));
        }
        int uB = (kk + bkof) >> 3;
#pragma unroll
        for (int np = 0; np < 4; np++) {
            uint32_t bd = sb + O_K_H + swz64(wn * 64 + np * 16 + brow, uB);
            uint32_t bh4[4], bl4[4];
            ldsm4(bh4, bd);
            ldsm4(bl4, bd + (O_K_L - O_K_H));
#pragma unroll
            for (int sub = 0; sub < 2; sub++) {
                int ni = np * 2 + sub;
                uint32_t b0h = bh4[sub * 2], b1h = bh4[sub * 2 + 1];
                uint32_t b0l = bl4[sub * 2], b1l = bl4[sub * 2 + 1];
#pragma unroll
                for (int mi = 0; mi < 2; mi++) {
                    mma_f16(acc1[mi][ni], ah[mi], b0h, b1h);
                    mma_f16(acc1[mi][ni], ah[mi], b0l, b1l);
                    mma_f16(acc1[mi][ni], al[mi], b0h, b1h);
                }
            }
        }
    }
    __syncthreads();

    // apply w_mat, store att hi/lo (256B rows, swzA)
#pragma unroll
    for (int mi = 0; mi < 2; mi++) {
        int r0 = wm * 32 + mi * 16 + g;
        int r1 = r0 + 8;
#pragma unroll
        for (int ni = 0; ni < 8; ni++) {
            int cc = wn * 64 + ni * 8 + 2 * t;
            int d;
            d = r0 - cc;     float w00 = (d > 0) ? dp[d - 1] : ((d == 0) ? uf : 0.f);
            d = r0 - cc - 1; float w01 = (d > 0) ? dp[d - 1] : ((d == 0) ? uf : 0.f);
            d = r1 - cc;     float w10 = (d > 0) ? dp[d - 1] : ((d == 0) ? uf : 0.f);
            d = r1 - cc - 1; float w11 = (d > 0) ? dp[d - 1] : ((d == 0) ? uf : 0.f);
            float a0 = acc1[mi][ni][0] * w00, a1 = acc1[mi][ni][1] * w01;
            float a2 = acc1[mi][ni][2] * w10, a3 = acc1[mi][ni][3] * w11;
            uint32_t o0 = swzA(r0, cc >> 3) + (cc & 7) * 2;
            uint32_t o1 = swzA(r1, cc >> 3) + (cc & 7) * 2;
            uint32_t hA = h2pack(a0, a1), hB = h2pack(a2, a3);
            *(uint32_t*)(sm + O_ATT_H + o0) = hA;
            *(uint32_t*)(sm + O_ATT_H + o1) = hB;
            __half2 hAv = *(__half2*)&hA;
            __half2 hBv = *(__half2*)&hB;
            *(uint32_t*)(sm + O_ATT_L + o0) =
                h2pack(a0 - __half2float(hAv.x), a1 - __half2float(hAv.y));
            *(uint32_t*)(sm + O_ATT_L + o1) =
                h2pack(a2 - __half2float(hBv.x), a3 - __half2float(hBv.y));
        }
    }
    __syncthreads();

    // ---- P2: out = att @ v + (r @ s) * dp[row] ----
    float acc2[2][4][4], acc3[2][4][4];
#pragma unroll
    for (int mi = 0; mi < 2; mi++)
#pragma unroll
        for (int ni = 0; ni < 4; ni++)
#pragma unroll
            for (int q = 0; q < 4; q++) { acc2[mi][ni][q] = 0.f; acc3[mi][ni][q] = 0.f; }

    int trow_lo = ((lane >> 3) & 1) * 8 + (lane & 7);
    int tui = lane >> 4;
#pragma unroll
    for (int ks = 0; ks < 8; ks++) {
        int kk = ks * 16;
        int uA = (kk + akof) >> 3;
        uint32_t ah[2][4], al[2][4];
#pragma unroll
        for (int mi = 0; mi < 2; mi++) {
            uint32_t ad = sb + O_ATT_H + swzA(wm * 32 + mi * 16 + arow, uA);
            ldsm4(ah[mi], ad);
            ldsm4(al[mi], ad + (O_ATT_L - O_ATT_H));
        }
#pragma unroll
        for (int np = 0; np < 2; np++) {
            int nb = wn * 32 + np * 16;
            uint32_t bd = sb + O_V_H + swz64(kk + trow_lo, (nb >> 3) + tui);
            uint32_t bh4[4], bl4[4];
            ldsm4t(bh4, bd);
            ldsm4t(bl4, bd + (O_V_L - O_V_H));
#pragma unroll
            for (int sub = 0; sub < 2; sub++) {
                int ni = np * 2 + sub;
                uint32_t b0h = bh4[sub * 2], b1h = bh4[sub * 2 + 1];
                uint32_t b0l = bl4[sub * 2], b1l = bl4[sub * 2 + 1];
#pragma unroll
                for (int mi = 0; mi < 2; mi++) {
                    mma_f16(acc2[mi][ni], ah[mi], b0h, b1h);
                    mma_f16(acc2[mi][ni], ah[mi], b0l, b1l);
                    mma_f16(acc2[mi][ni], al[mi], b0h, b1h);
                }
            }
        }
    }
#pragma unroll
    for (int ks = 0; ks < 4; ks++) {
        int kk = ks * 16;
        int uA = (kk + akof) >> 3;
        uint32_t ah[2][4], al[2][4];
#pragma unroll
        for (int mi = 0; mi < 2; mi++) {
            uint32_t ad = sb + O_R_H + swz64(wm * 32 + mi * 16 + arow, uA);
            ldsm4(ah[mi], ad);
            ldsm4(al[mi], ad + (O_R_L - O_R_H));
        }
#pragma unroll
        for (int np = 0; np < 2; np++) {
            int nb = wn * 32 + np * 16;
            uint32_t bd = sb + O_S_H + swz64(kk + trow_lo, (nb >> 3) + tui);
            uint32_t bh4[4], bl4[4];
            ldsm4t(bh4, bd);
            ldsm4t(bl4, bd + (O_S_L - O_S_H));
#pragma unroll
            for (int sub = 0; sub < 2; sub++) {
                int ni = np * 2 + sub;
                uint32_t b0h = bh4[sub * 2], b1h = bh4[sub * 2 + 1];
                uint32_t b0l = bl4[sub * 2], b1l = bl4[sub * 2 + 1];
#pragma unroll
                for (int mi = 0; mi < 2; mi++) {
                    mma_f16(acc3[mi][ni], ah[mi], b0h, b1h);
                    mma_f16(acc3[mi][ni], ah[mi], b0l, b1l);
                    mma_f16(acc3[mi][ni], al[mi], b0h, b1h);
                }
            }
        }
    }

    // ---- epilogue: y = out/8, GroupNorm over 64 ch, *lnw+lnb, *silu(g) ----
    float2* red = (float2*)(sm + O_RED);
#pragma unroll
    for (int mi = 0; mi < 2; mi++) {
        int r0 = wm * 32 + mi * 16 + g, r1 = r0 + 8;
        float d0 = dp[r0], d1 = dp[r1];
        float sA = 0.f, qA = 0.f, sB = 0.f, qB = 0.f;
#pragma unroll
        for (int ni = 0; ni < 4; ni++) {
            float y0 = (acc2[mi][ni][0] + d0 * acc3[mi][ni][0]) * 0.125f;
            float y1 = (acc2[mi][ni][1] + d0 * acc3[mi][ni][1]) * 0.125f;
            float y2 = (acc2[mi][ni][2] + d1 * acc3[mi][ni][2]) * 0.125f;
            float y3 = (acc2[mi][ni][3] + d1 * acc3[mi][ni][3]) * 0.125f;
            acc2[mi][ni][0] = y0; acc2[mi][ni][1] = y1;
            acc2[mi][ni][2] = y2; acc2[mi][ni][3] = y3;
            sA += y0 + y1; qA += y0 * y0 + y1 * y1;
            sB += y2 + y3; qB += y2 * y2 + y3 * y3;
        }
#pragma unroll
        for (int o = 1; o < 4; o <<= 1) {
            sA += __shfl_xor_sync(0xffffffffu, sA, o);
            qA += __shfl_xor_sync(0xffffffffu, qA, o);
            sB += __shfl_xor_sync(0xffffffffu, sB, o);
            qB += __shfl_xor_sync(0xffffffffu, qB, o);
        }
        if (t == 0) {
            red[r0 * 2 + wn] = make_float2(sA, qA);
            red[r1 * 2 + wn] = make_float2(sB, qB);
        }
    }
    __syncthreads();
#pragma unroll
    for (int mi = 0; mi < 2; mi++) {
        int r0 = wm * 32 + mi * 16 + g, r1 = r0 + 8;
        float2 pa = red[r0 * 2], pb = red[r0 * 2 + 1];
        float mu0 = (pa.x + pb.x) * (1.f / 64.f);
        float var0 = (pa.y + pb.y) * (1.f / 64.f) - mu0 * mu0;
        float inv0 = rsqrtf(var0 + 1e-5f);
        pa = red[r1 * 2]; pb = red[r1 * 2 + 1];
        float mu1 = (pa.x + pb.x) * (1.f / 64.f);
        float var1 = (pa.y + pb.y) * (1.f / 64.f) - mu1 * mu1;
        float inv1 = rsqrtf(var1 + 1e-5f);
#pragma unroll
        for (int ni = 0; ni < 4; ni++) {
            int cc = wn * 32 + ni * 8 + 2 * t;
            float lw0 = lws[cc], lw1 = lws[cc + 1];
            float lb0 = lbs[cc], lb1 = lbs[cc + 1];
            float2 gA = *(const float2*)(g_g + base + (size_t)r0 * CC + cc);
            float2 gB = *(const float2*)(g_g + base + (size_t)r1 * CC + cc);
            float s0g = gA.x / (1.f + expf(-gA.x));
            float s1g = gA.y / (1.f + expf(-gA.y));
            float s2g = gB.x / (1.f + expf(-gB.x));
            float s3g = gB.y / (1.f + expf(-gB.y));
            float z0 = ((acc2[mi][ni][0] - mu0) * inv0 * lw0 + lb0) * s0g;
            float z1 = ((acc2[mi][ni][1] - mu0) * inv0 * lw1 + lb1) * s1g;
            float z2 = ((acc2[mi][ni][2] - mu1) * inv1 * lw0 + lb0) * s2g;
            float z3 = ((acc2[mi][ni][3] - mu1) * inv1 * lw1 + lb1) * s3g;
            size_t i0 = base + (size_t)r0 * CC + cc;
            size_t i1 = base + (size_t)r1 * CC + cc;
            *(uint32_t*)(g_z + i0) = h2pack(z0, z1);
            *(uint32_t*)(g_z + i1) = h2pack(z2, z3);
        }
    }
}

// ---------------- launch ---------------------------------------------------
extern "C" void kernel_launch(void* const* d_in, const int* in_sizes, int n_in,
                              void* d_out, int out_size) {
    const float* xq     = (const float*)d_in[0];
    const float* tmk    = (const float*)d_in[1];
    const float* tmv    = (const float*)d_in[2];
    const float* tmr    = (const float*)d_in[3];
    const float* tmg    = (const float*)d_in[4];
    const float* tdecay = (const float*)d_in[5];
    const float* tfa    = (const float*)d_in[6];
    const float* Wr     = (const float*)d_in[7];
    const float* Wk     = (const float*)d_in[8];
    const float* Wv     = (const float*)d_in[9];
    const float* Wg     = (const float*)d_in[10];
    const float* Wo     = (const float*)d_in[11];
    const float* lnw    = (const float*)d_in[12];
    const float* lnb    = (const float*)d_in[13];
    float* out = (float*)d_out;

    __half *pxr, *pxk, *pxv, *pxg, *pz;
    __half *pwr, *pwk, *pwv, *pwg, *pwo;
    float *pr, *pk, *pv, *pg;
    cudaGetSymbolAddress((void**)&pxr, g_xr);
    cudaGetSymbolAddress((void**)&pxk, g_xk);
    cudaGetSymbolAddress((void**)&pxv, g_xv);
    cudaGetSymbolAddress((void**)&pxg, g_xg);
    cudaGetSymbolAddress((void**)&pz,  g_z);
    cudaGetSymbolAddress((void**)&pwr, g_wr); cudaGetSymbolAddress((void**)&pwk, g_wk);
    cudaGetSymbolAddress((void**)&pwv, g_wv); cudaGetSymbolAddress((void**)&pwg, g_wg);
    cudaGetSymbolAddress((void**)&pwo, g_wo);
    cudaGetSymbolAddress((void**)&pr, g_r); cudaGetSymbolAddress((void**)&pk, g_k);
    cudaGetSymbolAddress((void**)&pv, g_v); cudaGetSymbolAddress((void**)&pg, g_g);

    wsplit5_kernel<<<dim3(CC * CC / 256, 5), 256>>>(
        Wr, Wk, Wv, Wg, Wo, pwr, pwk, pwv, pwg, pwo);

    mix_kernel<<<MM * CC / 1024, 256>>>(xq, tmk, tmv, tmr, tmg);

    cudaFuncSetAttribute(gemm_mma, cudaFuncAttributeMaxDynamicSharedMemorySize,
                         GSM_TOTAL);
    gemm_mma<<<dim3(CC / 128, MM / 128, 4), 256, GSM_TOTAL>>>(
        pxr, pwr, pr,
        pxk, pwk, pk,
        pxv, pwv, pv,
        pxg, pwg, pg);

    cudaFuncSetAttribute(stateA_kernel, cudaFuncAttributeMaxDynamicSharedMemorySize,
                         ST_TOTAL);
    stateA_kernel<<<BB * HH * NCH, 256, ST_TOTAL>>>(tdecay);
    stateScan_kernel<<<BB * HH, 256>>>(tdecay);

    cudaFuncSetAttribute(out_mma_kernel, cudaFuncAttributeMaxDynamicSharedMemorySize,
                         O_TOTAL);
    out_mma_kernel<<<BB * HH * NCH, 256, O_TOTAL>>>(tdecay, tfa, lnw, lnb);

    gemm_mma<<<dim3(CC / 128, MM / 128, 1), 256, GSM_TOTAL>>>(
        pz, pwo, out,
        pz, pwo, out,
        pz, pwo, out,
        pz, pwo, out);
}